// round 12
// baseline (speedup 1.0000x reference)
#include <cuda_runtime.h>
#include <mma.h>
using namespace nvcuda;

// Problem constants
#define kN 50000
#define kNpad 50176   // padded per-relation row stride (196*256) for BM=256 stores
#define kR 3
#define kE 300000
#define kH 4
#define kD 32
#define kF 128
#define kOUT 64

// ---------------- scratch (device globals; no allocations allowed) ----------
__device__ __align__(16) float g_feat[(size_t)kR * kNpad * kF];  // projected features
__device__ __align__(16) float g_el[(size_t)kR * kN * kH];
__device__ __align__(16) float g_er[(size_t)kR * kN * kH];
__device__ __align__(16) float g_h[(size_t)kN * kF];             // layer outputs
// CSR (built once per launch; edges shared by both layers)
__device__ int g_hist[kR * kN];      // in-degree per (r, node)
__device__ int g_rowptr[kR * kN];    // exclusive prefix (per-relation local)
__device__ int g_cursor[kR * kN];    // scatter cursors
__device__ int g_edge[(size_t)kR * kE];  // src node ids, grouped by dst

// ---------------- zero hist --------------------------------------------------
__global__ void zero_hist_kernel() {
    int idx = blockIdx.x * blockDim.x + threadIdx.x;
    if (idx < kR * kN) g_hist[idx] = 0;
}

// ---------------- CSR build --------------------------------------------------
__global__ void hist_kernel(const int* __restrict__ edges) {
    int idx = blockIdx.x * blockDim.x + threadIdx.x;
    if (idx >= kR * kE) return;
    int r = idx / kE, e = idx % kE;
    int dst = edges[(size_t)r * 2 * kE + kE + e];
    atomicAdd(&g_hist[r * kN + dst], 1);
}

// One block per relation; 1024 threads; chunked sequential + Hillis-Steele scan.
__global__ __launch_bounds__(1024) void scan_kernel() {
    __shared__ int sums[1024];
    int r = blockIdx.x;
    int t = threadIdx.x;
    const int CH = (kN + 1023) / 1024;  // 49
    int begin = t * CH;
    int end = min(begin + CH, kN);
    int s = 0;
    for (int i = begin; i < end; i++) s += g_hist[r * kN + i];
    sums[t] = s;
    __syncthreads();
    for (int off = 1; off < 1024; off <<= 1) {
        int v = (t >= off) ? sums[t - off] : 0;
        __syncthreads();
        sums[t] += v;
        __syncthreads();
    }
    int running = sums[t] - s;  // exclusive
    for (int i = begin; i < end; i++) {
        g_rowptr[r * kN + i] = running;
        g_cursor[r * kN + i] = running;
        running += g_hist[r * kN + i];
    }
}

__global__ void scatter_kernel(const int* __restrict__ edges) {
    int idx = blockIdx.x * blockDim.x + threadIdx.x;
    if (idx >= kR * kE) return;
    int r = idx / kE, e = idx % kE;
    const int* eb = edges + (size_t)r * 2 * kE;
    int src = eb[e];
    int dst = eb[kE + e];
    int pos = atomicAdd(&g_cursor[r * kN + dst], 1);
    g_edge[(size_t)r * kE + pos] = src;
}

// ---------------- GEMM (tf32 WMMA, BM=256, 64x64 warp tiles) + el/er epilogue
// feat[r] = A @ W[r]; B(128x128) staged once; A double-buffered BK=32.
// 8 warps: 4 along M (64 rows each) x 2 along N (64 cols each). 1 CTA/SM.
#define BS_LD 132
#define AS_LD 36
#define kBM 256
__global__ __launch_bounds__(256) void gemm_feat_tc(
    const float* __restrict__ A, const float* __restrict__ W,
    const float* __restrict__ al, const float* __restrict__ ar) {
    extern __shared__ float smem[];
    float* Bs = smem;                       // [128][BS_LD]
    float* As = smem + 128 * BS_LD;         // [2][kBM][AS_LD]

    int r = blockIdx.z;
    int m0 = blockIdx.x * kBM;
    const float* B = W + (size_t)r * kF * kF;
    float* C = g_feat + (size_t)r * kNpad * kF;

    int t = threadIdx.x;
    int w = t >> 5;
    int wm = w & 3;        // 64-row slab
    int wn = w >> 2;       // 64-col slab

    // Stage all of B (convert to tf32)
#pragma unroll
    for (int rep = 0; rep < 16; rep++) {
        int lin = rep * 256 + t;            // 4096 float4 slots
        int row = lin >> 5;
        int col = (lin & 31) * 4;
        float4 v = *(const float4*)(B + (size_t)row * kF + col);
        v.x = wmma::__float_to_tf32(v.x); v.y = wmma::__float_to_tf32(v.y);
        v.z = wmma::__float_to_tf32(v.z); v.w = wmma::__float_to_tf32(v.w);
        *(float4*)&Bs[row * BS_LD + col] = v;
    }
    // Stage A chunk 0: 256 rows x 32 cols = 2048 float4 slots, 8 per thread
#pragma unroll
    for (int g = 0; g < 8; g++) {
        int lin = g * 256 + t;
        int rr = lin >> 3;
        int cc = (lin & 7) * 4;
        int gr = m0 + rr;
        float4 v = make_float4(0.f, 0.f, 0.f, 0.f);
        if (gr < kN) v = *(const float4*)(A + (size_t)gr * kF + cc);
        v.x = wmma::__float_to_tf32(v.x); v.y = wmma::__float_to_tf32(v.y);
        v.z = wmma::__float_to_tf32(v.z); v.w = wmma::__float_to_tf32(v.w);
        *(float4*)&As[rr * AS_LD + cc] = v;
    }
    __syncthreads();

    wmma::fragment<wmma::accumulator, 16, 16, 8, float> acc[4][4];
#pragma unroll
    for (int i = 0; i < 4; i++)
#pragma unroll
        for (int j = 0; j < 4; j++) wmma::fill_fragment(acc[i][j], 0.f);

#pragma unroll
    for (int c = 0; c < 4; c++) {
        float4 pf[8];
        if (c < 3) {
#pragma unroll
            for (int g = 0; g < 8; g++) {
                int lin = g * 256 + t;
                int rr = lin >> 3;
                int cc = (lin & 7) * 4;
                int gr = m0 + rr;
                float4 v = make_float4(0.f, 0.f, 0.f, 0.f);
                if (gr < kN) v = *(const float4*)(A + (size_t)gr * kF + (c + 1) * 32 + cc);
                pf[g] = v;
            }
        }
        const float* Ab = As + (c & 1) * kBM * AS_LD;
#pragma unroll
        for (int kk = 0; kk < 4; kk++) {
            wmma::fragment<wmma::matrix_a, 16, 16, 8, wmma::precision::tf32, wmma::row_major> fa[4];
            wmma::fragment<wmma::matrix_b, 16, 16, 8, wmma::precision::tf32, wmma::row_major> fb[4];
#pragma unroll
            for (int i = 0; i < 4; i++)
                wmma::load_matrix_sync(fa[i], Ab + (wm * 64 + i * 16) * AS_LD + kk * 8, AS_LD);
#pragma unroll
            for (int j = 0; j < 4; j++)
                wmma::load_matrix_sync(fb[j], Bs + (c * 32 + kk * 8) * BS_LD + wn * 64 + j * 16, BS_LD);
#pragma unroll
            for (int i = 0; i < 4; i++)
#pragma unroll
                for (int j = 0; j < 4; j++)
                    wmma::mma_sync(acc[i][j], fa[i], fb[j], acc[i][j]);
        }
        if (c < 3) {
            float* Anb = As + ((c + 1) & 1) * kBM * AS_LD;
#pragma unroll
            for (int g = 0; g < 8; g++) {
                int lin = g * 256 + t;
                int rr = lin >> 3;
                int cc = (lin & 7) * 4;
                float4 v = pf[g];
                v.x = wmma::__float_to_tf32(v.x); v.y = wmma::__float_to_tf32(v.y);
                v.z = wmma::__float_to_tf32(v.z); v.w = wmma::__float_to_tf32(v.w);
                *(float4*)&Anb[rr * AS_LD + cc] = v;
            }
            __syncthreads();
        }
    }
#pragma unroll
    for (int i = 0; i < 4; i++)
#pragma unroll
        for (int j = 0; j < 4; j++)
            wmma::store_matrix_sync(C + (size_t)(m0 + wm * 64 + i * 16) * kF + wn * 64 + j * 16,
                                    acc[i][j], kF, wmma::mem_row_major);

    // ---- epilogue: el/er for this block's 256 rows (C tile is L1-hot) ----
    __syncthreads();   // block-level fence: all warps' C stores visible
    int gr = m0 + t;
    if (gr < kN) {
        const float* crow = C + (size_t)gr * kF;
        const float* alr = al + r * kH * kD;
        const float* arr = ar + r * kH * kD;
#pragma unroll
        for (int h = 0; h < kH; h++) {
            float sl = 0.f, sr = 0.f;
#pragma unroll
            for (int d = 0; d < kD; d += 4) {
                float4 f  = *(const float4*)(crow + h * kD + d);
                float4 lv = *(const float4*)(alr + h * kD + d);
                float4 rv = *(const float4*)(arr + h * kD + d);
                sl += f.x * lv.x + f.y * lv.y + f.z * lv.z + f.w * lv.w;
                sr += f.x * rv.x + f.y * rv.y + f.z * rv.z + f.w * rv.w;
            }
            g_el[((size_t)r * kN + gr) * kH + h] = sl;
            g_er[((size_t)r * kN + gr) * kH + h] = sr;
        }
    }
}

// ---------------- aggregate (CSR, fused softmax): one warp per node ----------
// out = sum_r (sum_e feat_r[src]*ex_e) / (sum_e ex_e) + bias; optional relu.
// Batch-4 edge pipelining: 4 src idx -> 4 el + 4 feat loads in flight (MLP~8).
__global__ __launch_bounds__(256) void aggregate_kernel(
    const float* __restrict__ b, int do_relu) {
    int gid = blockIdx.x * blockDim.x + threadIdx.x;
    int n = gid >> 5;
    int lane = gid & 31;
    if (n >= kN) return;
    int h = lane >> 3;        // head for this lane's 4 columns
    int col = lane * 4;
    float4 tot = make_float4(0.f, 0.f, 0.f, 0.f);
#pragma unroll
    for (int r = 0; r < kR; r++) {
        int base = g_rowptr[r * kN + n];
        int deg  = g_hist[r * kN + n];
        if (deg == 0) continue;
        float erh = g_er[((size_t)r * kN + n) * kH + h];
        const float* featr = g_feat + (size_t)r * kNpad * kF;
        const float* elp = g_el + (size_t)r * kN * kH;
        const int* srcs = g_edge + (size_t)r * kE + base;
        float4 acc = make_float4(0.f, 0.f, 0.f, 0.f);
        float dsum = 0.f;
        int k = 0;
        for (; k + 4 <= deg; k += 4) {
            int s0 = srcs[k + 0], s1 = srcs[k + 1], s2 = srcs[k + 2], s3 = srcs[k + 3];
            float e0 = elp[(size_t)s0 * kH + h];
            float e1 = elp[(size_t)s1 * kH + h];
            float e2 = elp[(size_t)s2 * kH + h];
            float e3 = elp[(size_t)s3 * kH + h];
            float4 f0 = *(const float4*)(featr + (size_t)s0 * kF + col);
            float4 f1 = *(const float4*)(featr + (size_t)s1 * kF + col);
            float4 f2 = *(const float4*)(featr + (size_t)s2 * kF + col);
            float4 f3 = *(const float4*)(featr + (size_t)s3 * kF + col);
            e0 += erh; e0 = (e0 >= 0.f) ? e0 : 0.2f * e0; float x0 = __expf(e0);
            e1 += erh; e1 = (e1 >= 0.f) ? e1 : 0.2f * e1; float x1 = __expf(e1);
            e2 += erh; e2 = (e2 >= 0.f) ? e2 : 0.2f * e2; float x2 = __expf(e2);
            e3 += erh; e3 = (e3 >= 0.f) ? e3 : 0.2f * e3; float x3 = __expf(e3);
            acc.x += f0.x * x0 + f1.x * x1 + f2.x * x2 + f3.x * x3;
            acc.y += f0.y * x0 + f1.y * x1 + f2.y * x2 + f3.y * x3;
            acc.z += f0.z * x0 + f1.z * x1 + f2.z * x2 + f3.z * x3;
            acc.w += f0.w * x0 + f1.w * x1 + f2.w * x2 + f3.w * x3;
            dsum += x0 + x1 + x2 + x3;
        }
        for (; k < deg; k++) {
            int s = srcs[k];
            float e = elp[(size_t)s * kH + h] + erh;
            e = (e >= 0.f) ? e : 0.2f * e;
            float ex = __expf(e);
            float4 f = *(const float4*)(featr + (size_t)s * kF + col);
            acc.x += f.x * ex; acc.y += f.y * ex;
            acc.z += f.z * ex; acc.w += f.w * ex;
            dsum += ex;
        }
        float inv = 1.f / dsum;
        tot.x += acc.x * inv; tot.y += acc.y * inv;
        tot.z += acc.z * inv; tot.w += acc.w * inv;
    }
    // bias summed over relations
    float4 b0 = *(const float4*)(b + col);
    float4 b1 = *(const float4*)(b + kF + col);
    float4 b2 = *(const float4*)(b + 2 * kF + col);
    tot.x += b0.x + b1.x + b2.x;
    tot.y += b0.y + b1.y + b2.y;
    tot.z += b0.z + b1.z + b2.z;
    tot.w += b0.w + b1.w + b2.w;
    if (do_relu) {
        tot.x = fmaxf(tot.x, 0.f); tot.y = fmaxf(tot.y, 0.f);
        tot.z = fmaxf(tot.z, 0.f); tot.w = fmaxf(tot.w, 0.f);
    }
    *(float4*)(g_h + (size_t)n * kF + col) = tot;
}

// ---------------- final GEMM: out = g_h(N,128) @ Wl(128,64) + bl -------------
__global__ __launch_bounds__(256) void gemm_out_kernel(
    const float* __restrict__ A, const float* __restrict__ B,
    const float* __restrict__ bl, float* __restrict__ C) {
    int m0 = blockIdx.x * 128;
    __shared__ float As[8][128];
    __shared__ float Bs[8][64];
    int t = threadIdx.x;
    int ty = t >> 4;
    int tx = t & 15;
    float acc[8][4];
#pragma unroll
    for (int i = 0; i < 8; i++)
#pragma unroll
        for (int j = 0; j < 4; j++) acc[i][j] = 0.f;

    for (int k0 = 0; k0 < kF; k0 += 8) {
        {
            int row = t >> 1;
            int seg = (t & 1) * 4;
            int gr = m0 + row;
            float4 a4 = make_float4(0.f, 0.f, 0.f, 0.f);
            if (gr < kN) a4 = *(const float4*)(A + (size_t)gr * kF + k0 + seg);
            As[seg + 0][row] = a4.x; As[seg + 1][row] = a4.y;
            As[seg + 2][row] = a4.z; As[seg + 3][row] = a4.w;
            if (t < 128) {
                int brow = t >> 4;
                int bcol = (t & 15) * 4;
                *(float4*)(&Bs[brow][bcol]) = *(const float4*)(B + (size_t)(k0 + brow) * kOUT + bcol);
            }
        }
        __syncthreads();
#pragma unroll
        for (int kk = 0; kk < 8; kk++) {
            float ra[8], rb[4];
#pragma unroll
            for (int i = 0; i < 8; i++) ra[i] = As[kk][ty * 8 + i];
#pragma unroll
            for (int j = 0; j < 4; j++) rb[j] = Bs[kk][tx * 4 + j];
#pragma unroll
            for (int i = 0; i < 8; i++)
#pragma unroll
                for (int j = 0; j < 4; j++) acc[i][j] += ra[i] * rb[j];
        }
        __syncthreads();
    }
#pragma unroll
    for (int i = 0; i < 8; i++) {
        int gr = m0 + ty * 8 + i;
        if (gr < kN) {
            float4 v = make_float4(acc[i][0] + bl[tx * 4 + 0], acc[i][1] + bl[tx * 4 + 1],
                                   acc[i][2] + bl[tx * 4 + 2], acc[i][3] + bl[tx * 4 + 3]);
            *(float4*)(C + (size_t)gr * kOUT + tx * 4) = v;
        }
    }
}

extern "C" void kernel_launch(void* const* d_in, const int* in_sizes, int n_in,
                              void* d_out, int out_size) {
    const float* x     = (const float*)d_in[0];
    const int*   edges = (const int*)d_in[1];   // JAX x64 disabled -> int32
    const float* W1    = (const float*)d_in[2];
    const float* al1   = (const float*)d_in[3];
    const float* ar1   = (const float*)d_in[4];
    const float* b1    = (const float*)d_in[5];
    const float* W2    = (const float*)d_in[6];
    const float* al2   = (const float*)d_in[7];
    const float* ar2   = (const float*)d_in[8];
    const float* b2    = (const float*)d_in[9];
    const float* Wl    = (const float*)d_in[10];
    const float* bl    = (const float*)d_in[11];
    float*       out   = (float*)d_out;

    float* hbuf = nullptr;
    cudaGetSymbolAddress((void**)&hbuf, g_h);

    const int TB = 256;
    const int GEMM_SMEM = (128 * BS_LD + 2 * kBM * AS_LD) * 4;  // ~138 KB
    static int attr_set = 0;
    if (!attr_set) {
        cudaFuncSetAttribute(gemm_feat_tc, cudaFuncAttributeMaxDynamicSharedMemorySize, GEMM_SMEM);
        attr_set = 1;
    }
    dim3 gemm_grid((kN + kBM - 1) / kBM, 1, kR);

    // ---- CSR build + layer-1 GEMM (gemm placed at launch #3 for profiling) ----
    zero_hist_kernel<<<(kR * kN + TB - 1) / TB, TB>>>();
    hist_kernel<<<(kR * kE + TB - 1) / TB, TB>>>(edges);
    scan_kernel<<<kR, 1024>>>();
    gemm_feat_tc<<<gemm_grid, TB, GEMM_SMEM>>>(x, W1, al1, ar1);     // launch #3 (profiled)
    scatter_kernel<<<(kR * kE + TB - 1) / TB, TB>>>(edges);

    // ---- layer 1 aggregate ----
    aggregate_kernel<<<(kN * 32 + TB - 1) / TB, TB>>>(b1, 1);

    // ---- layer 2 ----
    gemm_feat_tc<<<gemm_grid, TB, GEMM_SMEM>>>(hbuf, W2, al2, ar2);
    aggregate_kernel<<<(kN * 32 + TB - 1) / TB, TB>>>(b2, 0);

    // ---- final linear ----
    gemm_out_kernel<<<(kN + 127) / 128, TB>>>(hbuf, Wl, bl, out);
}